// round 6
// baseline (speedup 1.0000x reference)
#include <cuda_runtime.h>

#define NN  50000
#define FI  96
#define HID 128
#define FO  64
#define NE  800000

typedef unsigned long long u64;

// ---------------- device scratch (no allocations allowed) ----------------
__device__ __align__(16) int   g_src[NE];
__device__ __align__(16) int   g_dst[NE];
__device__ __align__(16) int   g_deg[NN];
__device__ __align__(16) int   g_off[NN + 1];
__device__ __align__(16) int   g_cur[NN];
__device__ __align__(16) int   g_csr_src[NE];
__device__ __align__(16) float g_agg1[(size_t)NN * FI];   // 19.2 MB
__device__ __align__(16) float g_h[(size_t)NN * HID];     // 25.6 MB
__device__ __align__(16) float g_p[(size_t)NN * FO];      // 12.8 MB
__device__ int g_is64;

// ---------------- f32x2 helpers (sm_103a packed FP32) ----------------
__device__ __forceinline__ u64 fma2(u64 a, u64 b, u64 c) {
    u64 d;
    asm("fma.rn.f32x2 %0, %1, %2, %3;" : "=l"(d) : "l"(a), "l"(b), "l"(c));
    return d;
}
__device__ __forceinline__ u64 lds_u64(const float* p) {
    u64 v;
    unsigned a = (unsigned)__cvta_generic_to_shared(p);
    asm("ld.shared.b64 %0, [%1];" : "=l"(v) : "r"(a));
    return v;
}
__device__ __forceinline__ void lds_v2u64(const float* p, u64& x, u64& y) {
    unsigned a = (unsigned)__cvta_generic_to_shared(p);
    asm("ld.shared.v2.u64 {%0, %1}, [%2];" : "=l"(x), "=l"(y) : "r"(a));
}
__device__ __forceinline__ float2 u2f(u64 v) {
    float2 f;
    asm("mov.b64 {%0, %1}, %2;" : "=f"(f.x), "=f"(f.y) : "l"(v));
    return f;
}
__device__ __forceinline__ void f4add(float4& a, float4 b) {
    a.x += b.x; a.y += b.y; a.z += b.z; a.w += b.w;
}

// ---------------- dtype detect: int64 edge_index has all-odd-int32-words == 0 ----------------
__global__ void k_detect(const int* __restrict__ ei32) {
    __shared__ int nz;
    if (threadIdx.x == 0) nz = 0;
    __syncthreads();
    if (ei32[2 * threadIdx.x + 1] != 0) atomicAdd(&nz, 1);
    __syncthreads();
    if (threadIdx.x == 0) g_is64 = (nz == 0) ? 1 : 0;
}

// ---------------- zero degree counters ----------------
__global__ void k_zero_deg() {
    int i = blockIdx.x * blockDim.x + threadIdx.x;
    if (i < NN) g_deg[i] = 0;
}

// ---------------- convert + per-dst histogram ----------------
__global__ void k_convert(const void* __restrict__ ei) {
    int e = blockIdx.x * blockDim.x + threadIdx.x;
    if (e >= NE) return;
    int s, d;
    if (g_is64) {
        const long long* p = (const long long*)ei;
        s = (int)p[e]; d = (int)p[NE + e];
    } else {
        const int* p = (const int*)ei;
        s = p[e]; d = p[NE + e];
    }
    if (s < 0 || s >= NN || d < 0 || d >= NN) { s = 0; d = 0; }  // treated as self-loop
    g_src[e] = s;
    g_dst[e] = d;
    if (s != d) atomicAdd(&g_deg[d], 1);
}

// ---------------- exclusive prefix scan over g_deg (single block) ----------------
#define SCAN_T 1024
#define CHUNK  ((NN + SCAN_T - 1) / SCAN_T)   // 49

__global__ __launch_bounds__(SCAN_T, 1) void k_scan() {
    __shared__ int part[SCAN_T];
    int t = threadIdx.x;
    int b = t * CHUNK;
    int e = min(b + CHUNK, NN);
    int s = 0;
    for (int i = b; i < e; i++) s += g_deg[i];
    part[t] = s;
    __syncthreads();
    // Hillis-Steele inclusive scan
    for (int ofs = 1; ofs < SCAN_T; ofs <<= 1) {
        int v = (t >= ofs) ? part[t - ofs] : 0;
        __syncthreads();
        part[t] += v;
        __syncthreads();
    }
    int run = part[t] - s;   // exclusive prefix
    for (int i = b; i < e; i++) {
        int d = g_deg[i];
        g_off[i] = run;
        g_cur[i] = run;
        run += d;
    }
    if (t == SCAN_T - 1) g_off[NN] = run;
}

// ---------------- CSR fill: csr_src grouped by dst ----------------
__global__ void k_fill() {
    int e = blockIdx.x * blockDim.x + threadIdx.x;
    if (e >= NE) return;
    int s = g_src[e], d = g_dst[e];
    if (s == d) return;
    int pos = atomicAdd(&g_cur[d], 1);
    g_csr_src[pos] = s;
}

// ---------------- agg1 gather: agg1[n] = sum_{e: dst=n} x[src[e]], 8 thr/node ----------------
__global__ void k_agg1(const float* __restrict__ x) {
    int gid = blockIdx.x * blockDim.x + threadIdx.x;
    int node = gid >> 3;
    int c = gid & 7;
    if (node >= NN) return;
    int i = g_off[node], end = g_off[node + 1];
    float4 a0 = make_float4(0.f, 0.f, 0.f, 0.f), a1 = a0, a2 = a0;
    int s = (i < end) ? g_csr_src[i] : 0;
    while (i < end) {
        int snext = (i + 1 < end) ? g_csr_src[i + 1] : 0;
        const float4* xs = (const float4*)(x + (size_t)s * FI);
        f4add(a0, xs[c]);
        f4add(a1, xs[c + 8]);
        f4add(a2, xs[c + 16]);
        s = snext;
        i++;
    }
    float4* ad = (float4*)(g_agg1 + (size_t)node * FI);
    ad[c] = a0; ad[c + 8] = a1; ad[c + 16] = a2;
}

// ---------------- gemm1: h = relu(agg1@W1_rel^T + x@W1_root^T + b1), FFMA2 ----------------
// 512 thr (16 warps); warp handles 4 nodes, lane covers 4 of 128 outputs.
// stage: activations duplicated as (a,a) pairs for ld.shared.b64 broadcast.
#define G1_SMEM_FLOATS (24576 + 128 + 16 * 1536)   // 49280 floats = 197120 B

__global__ __launch_bounds__(512, 1)
void k_gemm1(const float* __restrict__ x, const float* __restrict__ Wrel,
             const float* __restrict__ b, const float* __restrict__ Wroot) {
    extern __shared__ float sm[];
    float* sb    = sm + 24576;
    float* stage = sm + 24704;
    int tid  = threadIdx.x;
    int warp = tid >> 5, lane = tid & 31;

    for (int i = tid; i < 12288; i += 512) {   // transpose both W's: [96][128]
        int j = i / FI, k = i - j * FI;
        sm[k * HID + j]         = Wrel[i];
        sm[12288 + k * HID + j] = Wroot[i];
    }
    if (tid < HID) sb[tid] = b[tid];
    __syncthreads();

    float* aD = stage + warp * 1536;   // [4 nodes][96 k] as (a,a) float pairs
    float* xD = aD + 768;
    const float* wrB = sm + lane * 4;
    const float* woB = sm + 12288 + lane * 4;

    for (int g = blockIdx.x * 16 + warp; g < NN / 4; g += gridDim.x * 16) {
        int node0 = g * 4;
        __syncwarp();
        const float4* ap = (const float4*)(g_agg1 + (size_t)node0 * FI); // 96 float4
        const float4* xp = (const float4*)(x      + (size_t)node0 * FI);
#pragma unroll
        for (int i = 0; i < 3; i++) {
            int f = lane + 32 * i;          // 0..95
            int nd = f / 24, k4 = f - nd * 24;
            float4 a = ap[f];
            float4 v = xp[f];
            float4* da = ((float4*)(aD + nd * 192)) + k4 * 2;
            da[0] = make_float4(a.x, a.x, a.y, a.y);
            da[1] = make_float4(a.z, a.z, a.w, a.w);
            float4* dx = ((float4*)(xD + nd * 192)) + k4 * 2;
            dx[0] = make_float4(v.x, v.x, v.y, v.y);
            dx[1] = make_float4(v.z, v.z, v.w, v.w);
        }
        __syncwarp();

        u64 acc[4][2];
#pragma unroll
        for (int n = 0; n < 4; n++) { acc[n][0] = 0ull; acc[n][1] = 0ull; }

#pragma unroll 2
        for (int k = 0; k < FI; k++) {
            u64 wr0, wr1, wo0, wo1;
            lds_v2u64(wrB + k * HID, wr0, wr1);
            lds_v2u64(woB + k * HID, wo0, wo1);
#pragma unroll
            for (int n = 0; n < 4; n++) {
                u64 aa = lds_u64(aD + n * 192 + k * 2);
                u64 vv = lds_u64(xD + n * 192 + k * 2);
                acc[n][0] = fma2(aa, wr0, acc[n][0]);
                acc[n][1] = fma2(aa, wr1, acc[n][1]);
                acc[n][0] = fma2(vv, wo0, acc[n][0]);
                acc[n][1] = fma2(vv, wo1, acc[n][1]);
            }
        }
        float4 bb = ((const float4*)sb)[lane];
#pragma unroll
        for (int n = 0; n < 4; n++) {
            float2 lo = u2f(acc[n][0]), hi = u2f(acc[n][1]);
            float4 r;
            r.x = fmaxf(lo.x + bb.x, 0.f);
            r.y = fmaxf(lo.y + bb.y, 0.f);
            r.z = fmaxf(hi.x + bb.z, 0.f);
            r.w = fmaxf(hi.y + bb.w, 0.f);
            ((float4*)(g_h + (size_t)(node0 + n) * HID))[lane] = r;
        }
    }
}

// ---------------- gemm2: p = h@W2_rel^T ; out = h@W2_root^T + b2, FFMA2 ----------------
#define G2_SMEM_FLOATS (16384 + 64 + 16 * 1024)    // 32832 floats = 131328 B

__global__ __launch_bounds__(512, 1)
void k_gemm2(const float* __restrict__ Wrel, const float* __restrict__ b,
             const float* __restrict__ Wroot, float* __restrict__ out) {
    extern __shared__ float sm[];
    float* sb    = sm + 16384;
    float* stage = sm + 16448;
    int tid  = threadIdx.x;
    int warp = tid >> 5, lane = tid & 31;

    for (int i = tid; i < 8192; i += 512) {    // transpose both W's: [128][64]
        int j = i >> 7, k = i & 127;
        sm[k * FO + j]        = Wrel[i];
        sm[8192 + k * FO + j] = Wroot[i];
    }
    if (tid < FO) sb[tid] = b[tid];
    __syncthreads();

    float* hD = stage + warp * 1024;   // [4 nodes][128 k] as (h,h) pairs
    const float* wrB = sm + lane * 2;
    const float* woB = sm + 8192 + lane * 2;

    for (int g = blockIdx.x * 16 + warp; g < NN / 4; g += gridDim.x * 16) {
        int node0 = g * 4;
        __syncwarp();
        const float4* hp = (const float4*)(g_h + (size_t)node0 * HID); // 128 float4
#pragma unroll
        for (int i = 0; i < 4; i++) {
            int f = lane + 32 * i;          // 0..127
            int nd = f >> 5, k4 = f & 31;
            float4 h = hp[f];
            float4* dh = ((float4*)(hD + nd * 256)) + k4 * 2;
            dh[0] = make_float4(h.x, h.x, h.y, h.y);
            dh[1] = make_float4(h.z, h.z, h.w, h.w);
        }
        __syncwarp();

        u64 accP[4], accO[4];
#pragma unroll
        for (int n = 0; n < 4; n++) { accP[n] = 0ull; accO[n] = 0ull; }

#pragma unroll 4
        for (int k = 0; k < HID; k++) {
            u64 wr = lds_u64(wrB + k * FO);
            u64 wo = lds_u64(woB + k * FO);
#pragma unroll
            for (int n = 0; n < 4; n++) {
                u64 hh = lds_u64(hD + n * 256 + k * 2);
                accP[n] = fma2(hh, wr, accP[n]);
                accO[n] = fma2(hh, wo, accO[n]);
            }
        }
        float2 bb = ((const float2*)sb)[lane];
#pragma unroll
        for (int n = 0; n < 4; n++) {
            float2 pv = u2f(accP[n]);
            ((float2*)(g_p + (size_t)(node0 + n) * FO))[lane] = pv;
            float2 ov = u2f(accO[n]);
            ov.x += bb.x; ov.y += bb.y;
            ((float2*)(out + (size_t)(node0 + n) * FO))[lane] = ov;
        }
    }
}

// ---------------- agg2 gather: out[n] += sum_{e: dst=n} p[src[e]], 16 thr/node ----------------
__global__ void k_agg2(float* __restrict__ out) {
    int gid = blockIdx.x * blockDim.x + threadIdx.x;
    int node = gid >> 4;
    int c = gid & 15;
    if (node >= NN) return;
    int i = g_off[node], end = g_off[node + 1];
    float4 acc = make_float4(0.f, 0.f, 0.f, 0.f);
    int s = (i < end) ? g_csr_src[i] : 0;
    while (i < end) {
        int snext = (i + 1 < end) ? g_csr_src[i + 1] : 0;
        f4add(acc, ((const float4*)(g_p + (size_t)s * FO))[c]);
        s = snext;
        i++;
    }
    float4* od = (float4*)(out + (size_t)node * FO);
    float4 cur = od[c];
    f4add(cur, acc);
    od[c] = cur;
}

// ---------------- launch ----------------
extern "C" void kernel_launch(void* const* d_in, const int* in_sizes, int n_in,
                              void* d_out, int out_size) {
    const float* x       = (const float*)d_in[0];
    const void*  ei      = d_in[1];
    const float* W1_rel  = (const float*)d_in[2];
    const float* b1      = (const float*)d_in[3];
    const float* W1_root = (const float*)d_in[4];
    const float* W2_rel  = (const float*)d_in[5];
    const float* b2      = (const float*)d_in[6];
    const float* W2_root = (const float*)d_in[7];
    float* out = (float*)d_out;

    const int g1_smem = G1_SMEM_FLOATS * 4;   // 197120 B
    const int g2_smem = G2_SMEM_FLOATS * 4;   // 131328 B
    cudaFuncSetAttribute(k_gemm1, cudaFuncAttributeMaxDynamicSharedMemorySize, g1_smem);
    cudaFuncSetAttribute(k_gemm2, cudaFuncAttributeMaxDynamicSharedMemorySize, g2_smem);

    k_detect <<<1, 256>>>((const int*)ei);
    k_zero_deg<<<(NN + 255) / 256, 256>>>();
    k_convert<<<(NE + 255) / 256, 256>>>(ei);
    k_scan   <<<1, SCAN_T>>>();
    k_fill   <<<(NE + 255) / 256, 256>>>();
    k_agg1   <<<(NN * 8 + 255) / 256, 256>>>(x);
    k_gemm1  <<<148, 512, g1_smem>>>(x, W1_rel, b1, W1_root);
    k_gemm2  <<<148, 512, g2_smem>>>(W2_rel, b2, W2_root, out);
    k_agg2   <<<(NN * 16 + 255) / 256, 256>>>(out);
}

// round 7
// speedup vs baseline: 1.3044x; 1.3044x over previous
#include <cuda_runtime.h>

#define NN  50000
#define FI  96
#define HID 128
#define FO  64
#define NE  800000

typedef unsigned long long u64;

// ---------------- device scratch (no allocations allowed) ----------------
__device__ __align__(16) int   g_src[NE];
__device__ __align__(16) int   g_dst[NE];
__device__ __align__(16) int   g_deg[NN];
__device__ __align__(16) int   g_off[NN + 1];
__device__ __align__(16) int   g_cur[NN];
__device__ __align__(16) int   g_csr_src[NE];
__device__ __align__(16) float g_agg1[(size_t)NN * FI];   // 19.2 MB
__device__ __align__(16) float g_h[(size_t)NN * HID];     // 25.6 MB
__device__ __align__(16) float g_p[(size_t)NN * FO];      // 12.8 MB
__device__ int g_is64;

#define SB 512
#define NB ((NN + SB - 1) / SB)     // 98 scan blocks
__device__ int g_bsum[128];
__device__ int g_boff[128];

// ---------------- f32x2 helpers (sm_103a packed FP32) ----------------
__device__ __forceinline__ u64 fma2(u64 a, u64 b, u64 c) {
    u64 d;
    asm("fma.rn.f32x2 %0, %1, %2, %3;" : "=l"(d) : "l"(a), "l"(b), "l"(c));
    return d;
}
__device__ __forceinline__ u64 lds_u64(const float* p) {
    u64 v;
    unsigned a = (unsigned)__cvta_generic_to_shared(p);
    asm("ld.shared.b64 %0, [%1];" : "=l"(v) : "r"(a));
    return v;
}
__device__ __forceinline__ void lds_v2u64(const float* p, u64& x, u64& y) {
    unsigned a = (unsigned)__cvta_generic_to_shared(p);
    asm("ld.shared.v2.u64 {%0, %1}, [%2];" : "=l"(x), "=l"(y) : "r"(a));
}
__device__ __forceinline__ float2 u2f(u64 v) {
    float2 f;
    asm("mov.b64 {%0, %1}, %2;" : "=f"(f.x), "=f"(f.y) : "l"(v));
    return f;
}
__device__ __forceinline__ void f4add(float4& a, float4 b) {
    a.x += b.x; a.y += b.y; a.z += b.z; a.w += b.w;
}

// ---------------- init: zero degree counters; block 0 detects dtype ----------------
__global__ void k_init(const int* __restrict__ ei32) {
    int i = blockIdx.x * blockDim.x + threadIdx.x;
    if (i < NN) g_deg[i] = 0;
    if (blockIdx.x == 0) {
        __shared__ int nz;
        if (threadIdx.x == 0) nz = 0;
        __syncthreads();
        // int64 edge_index (values < 50000) has all odd int32 words == 0
        if (ei32[2 * threadIdx.x + 1] != 0) atomicAdd(&nz, 1);
        __syncthreads();
        if (threadIdx.x == 0) g_is64 = (nz == 0) ? 1 : 0;
    }
}

// ---------------- convert + per-dst histogram ----------------
__global__ void k_convert(const void* __restrict__ ei) {
    int e = blockIdx.x * blockDim.x + threadIdx.x;
    if (e >= NE) return;
    int s, d;
    if (g_is64) {
        const long long* p = (const long long*)ei;
        s = (int)p[e]; d = (int)p[NE + e];
    } else {
        const int* p = (const int*)ei;
        s = p[e]; d = p[NE + e];
    }
    if (s < 0 || s >= NN || d < 0 || d >= NN) { s = 0; d = 0; }  // treated as self-loop
    g_src[e] = s;
    g_dst[e] = d;
    if (s != d) atomicAdd(&g_deg[d], 1);
}

// ---------------- hierarchical exclusive scan: 98 blocks of 512 ----------------
__global__ __launch_bounds__(SB) void k_scan_a() {
    __shared__ int s[SB];
    int t = threadIdx.x;
    int i = blockIdx.x * SB + t;
    s[t] = (i < NN) ? g_deg[i] : 0;
    __syncthreads();
#pragma unroll
    for (int ofs = SB / 2; ofs > 0; ofs >>= 1) {
        if (t < ofs) s[t] += s[t + ofs];
        __syncthreads();
    }
    if (t == 0) g_bsum[blockIdx.x] = s[0];
}

__global__ __launch_bounds__(128) void k_scan_b() {
    __shared__ int s[128];
    int t = threadIdx.x;
    int v = (t < NB) ? g_bsum[t] : 0;
    s[t] = v;
    __syncthreads();
#pragma unroll
    for (int ofs = 1; ofs < 128; ofs <<= 1) {
        int u = (t >= ofs) ? s[t - ofs] : 0;
        __syncthreads();
        s[t] += u;
        __syncthreads();
    }
    g_boff[t] = s[t] - v;   // exclusive block offset
}

__global__ __launch_bounds__(SB) void k_scan_c() {
    __shared__ int s[SB];
    int t = threadIdx.x;
    int i = blockIdx.x * SB + t;
    int d = (i < NN) ? g_deg[i] : 0;
    s[t] = d;
    __syncthreads();
#pragma unroll
    for (int ofs = 1; ofs < SB; ofs <<= 1) {
        int u = (t >= ofs) ? s[t - ofs] : 0;
        __syncthreads();
        s[t] += u;
        __syncthreads();
    }
    if (i < NN) {
        int off = g_boff[blockIdx.x] + s[t] - d;   // exclusive
        g_off[i] = off;
        g_cur[i] = off;
        if (i == NN - 1) g_off[NN] = off + d;
    }
}

// ---------------- CSR fill: csr_src grouped by dst ----------------
__global__ void k_fill() {
    int e = blockIdx.x * blockDim.x + threadIdx.x;
    if (e >= NE) return;
    int s = g_src[e], d = g_dst[e];
    if (s == d) return;
    int pos = atomicAdd(&g_cur[d], 1);
    g_csr_src[pos] = s;
}

// ---------------- agg1 gather: agg1[n] = sum_{e: dst=n} x[src[e]], 8 thr/node ----------------
__global__ void k_agg1(const float* __restrict__ x) {
    int gid = blockIdx.x * blockDim.x + threadIdx.x;
    int node = gid >> 3;
    int c = gid & 7;
    if (node >= NN) return;
    int i = g_off[node], end = g_off[node + 1];
    float4 a0 = make_float4(0.f, 0.f, 0.f, 0.f), a1 = a0, a2 = a0;
    int s = (i < end) ? g_csr_src[i] : 0;
    while (i < end) {
        int snext = (i + 1 < end) ? g_csr_src[i + 1] : 0;
        const float4* xs = (const float4*)(x + (size_t)s * FI);
        f4add(a0, xs[c]);
        f4add(a1, xs[c + 8]);
        f4add(a2, xs[c + 16]);
        s = snext;
        i++;
    }
    float4* ad = (float4*)(g_agg1 + (size_t)node * FI);
    ad[c] = a0; ad[c + 8] = a1; ad[c + 16] = a2;
}

// ---------------- gemm1: h = relu(agg1@W1_rel^T + x@W1_root^T + b1), FFMA2 ----------------
#define G1_SMEM_FLOATS (24576 + 128 + 16 * 1536)   // 49280 floats = 197120 B

__global__ __launch_bounds__(512, 1)
void k_gemm1(const float* __restrict__ x, const float* __restrict__ Wrel,
             const float* __restrict__ b, const float* __restrict__ Wroot) {
    extern __shared__ float sm[];
    float* sb    = sm + 24576;
    float* stage = sm + 24704;
    int tid  = threadIdx.x;
    int warp = tid >> 5, lane = tid & 31;

    for (int i = tid; i < 12288; i += 512) {   // transpose both W's: [96][128]
        int j = i / FI, k = i - j * FI;
        sm[k * HID + j]         = Wrel[i];
        sm[12288 + k * HID + j] = Wroot[i];
    }
    if (tid < HID) sb[tid] = b[tid];
    __syncthreads();

    float* aD = stage + warp * 1536;   // [4 nodes][96 k] as (a,a) float pairs
    float* xD = aD + 768;
    const float* wrB = sm + lane * 4;
    const float* woB = sm + 12288 + lane * 4;

    for (int g = blockIdx.x * 16 + warp; g < NN / 4; g += gridDim.x * 16) {
        int node0 = g * 4;
        __syncwarp();
        const float4* ap = (const float4*)(g_agg1 + (size_t)node0 * FI); // 96 float4
        const float4* xp = (const float4*)(x      + (size_t)node0 * FI);
#pragma unroll
        for (int i = 0; i < 3; i++) {
            int f = lane + 32 * i;          // 0..95
            int nd = f / 24, k4 = f - nd * 24;
            float4 a = ap[f];
            float4 v = xp[f];
            float4* da = ((float4*)(aD + nd * 192)) + k4 * 2;
            da[0] = make_float4(a.x, a.x, a.y, a.y);
            da[1] = make_float4(a.z, a.z, a.w, a.w);
            float4* dx = ((float4*)(xD + nd * 192)) + k4 * 2;
            dx[0] = make_float4(v.x, v.x, v.y, v.y);
            dx[1] = make_float4(v.z, v.z, v.w, v.w);
        }
        __syncwarp();

        u64 acc[4][2];
#pragma unroll
        for (int n = 0; n < 4; n++) { acc[n][0] = 0ull; acc[n][1] = 0ull; }

#pragma unroll 2
        for (int k = 0; k < FI; k++) {
            u64 wr0, wr1, wo0, wo1;
            lds_v2u64(wrB + k * HID, wr0, wr1);
            lds_v2u64(woB + k * HID, wo0, wo1);
#pragma unroll
            for (int n = 0; n < 4; n++) {
                u64 aa = lds_u64(aD + n * 192 + k * 2);
                u64 vv = lds_u64(xD + n * 192 + k * 2);
                acc[n][0] = fma2(aa, wr0, acc[n][0]);
                acc[n][1] = fma2(aa, wr1, acc[n][1]);
                acc[n][0] = fma2(vv, wo0, acc[n][0]);
                acc[n][1] = fma2(vv, wo1, acc[n][1]);
            }
        }
        float4 bb = ((const float4*)sb)[lane];
#pragma unroll
        for (int n = 0; n < 4; n++) {
            float2 lo = u2f(acc[n][0]), hi = u2f(acc[n][1]);
            float4 r;
            r.x = fmaxf(lo.x + bb.x, 0.f);
            r.y = fmaxf(lo.y + bb.y, 0.f);
            r.z = fmaxf(hi.x + bb.z, 0.f);
            r.w = fmaxf(hi.y + bb.w, 0.f);
            ((float4*)(g_h + (size_t)(node0 + n) * HID))[lane] = r;
        }
    }
}

// ---------------- gemm2: p = h@W2_rel^T ; out = h@W2_root^T + b2, FFMA2 ----------------
#define G2_SMEM_FLOATS (16384 + 64 + 16 * 1024)    // 32832 floats = 131328 B

__global__ __launch_bounds__(512, 1)
void k_gemm2(const float* __restrict__ Wrel, const float* __restrict__ b,
             const float* __restrict__ Wroot, float* __restrict__ out) {
    extern __shared__ float sm[];
    float* sb    = sm + 16384;
    float* stage = sm + 16448;
    int tid  = threadIdx.x;
    int warp = tid >> 5, lane = tid & 31;

    for (int i = tid; i < 8192; i += 512) {    // transpose both W's: [128][64]
        int j = i >> 7, k = i & 127;
        sm[k * FO + j]        = Wrel[i];
        sm[8192 + k * FO + j] = Wroot[i];
    }
    if (tid < FO) sb[tid] = b[tid];
    __syncthreads();

    float* hD = stage + warp * 1024;   // [4 nodes][128 k] as (h,h) pairs
    const float* wrB = sm + lane * 2;
    const float* woB = sm + 8192 + lane * 2;

    for (int g = blockIdx.x * 16 + warp; g < NN / 4; g += gridDim.x * 16) {
        int node0 = g * 4;
        __syncwarp();
        const float4* hp = (const float4*)(g_h + (size_t)node0 * HID); // 128 float4
#pragma unroll
        for (int i = 0; i < 4; i++) {
            int f = lane + 32 * i;          // 0..127
            int nd = f >> 5, k4 = f & 31;
            float4 h = hp[f];
            float4* dh = ((float4*)(hD + nd * 256)) + k4 * 2;
            dh[0] = make_float4(h.x, h.x, h.y, h.y);
            dh[1] = make_float4(h.z, h.z, h.w, h.w);
        }
        __syncwarp();

        u64 accP[4], accO[4];
#pragma unroll
        for (int n = 0; n < 4; n++) { accP[n] = 0ull; accO[n] = 0ull; }

#pragma unroll 4
        for (int k = 0; k < HID; k++) {
            u64 wr = lds_u64(wrB + k * FO);
            u64 wo = lds_u64(woB + k * FO);
#pragma unroll
            for (int n = 0; n < 4; n++) {
                u64 hh = lds_u64(hD + n * 256 + k * 2);
                accP[n] = fma2(hh, wr, accP[n]);
                accO[n] = fma2(hh, wo, accO[n]);
            }
        }
        float2 bb = ((const float2*)sb)[lane];
#pragma unroll
        for (int n = 0; n < 4; n++) {
            float2 pv = u2f(accP[n]);
            ((float2*)(g_p + (size_t)(node0 + n) * FO))[lane] = pv;
            float2 ov = u2f(accO[n]);
            ov.x += bb.x; ov.y += bb.y;
            ((float2*)(out + (size_t)(node0 + n) * FO))[lane] = ov;
        }
    }
}

// ---------------- agg2 gather: out[n] += sum_{e: dst=n} p[src[e]], 16 thr/node ----------------
__global__ void k_agg2(float* __restrict__ out) {
    int gid = blockIdx.x * blockDim.x + threadIdx.x;
    int node = gid >> 4;
    int c = gid & 15;
    if (node >= NN) return;
    int i = g_off[node], end = g_off[node + 1];
    float4 acc = make_float4(0.f, 0.f, 0.f, 0.f);
    int s = (i < end) ? g_csr_src[i] : 0;
    while (i < end) {
        int snext = (i + 1 < end) ? g_csr_src[i + 1] : 0;
        f4add(acc, ((const float4*)(g_p + (size_t)s * FO))[c]);
        s = snext;
        i++;
    }
    float4* od = (float4*)(out + (size_t)node * FO);
    float4 cur = od[c];
    f4add(cur, acc);
    od[c] = cur;
}

// ---------------- launch ----------------
extern "C" void kernel_launch(void* const* d_in, const int* in_sizes, int n_in,
                              void* d_out, int out_size) {
    const float* x       = (const float*)d_in[0];
    const void*  ei      = d_in[1];
    const float* W1_rel  = (const float*)d_in[2];
    const float* b1      = (const float*)d_in[3];
    const float* W1_root = (const float*)d_in[4];
    const float* W2_rel  = (const float*)d_in[5];
    const float* b2      = (const float*)d_in[6];
    const float* W2_root = (const float*)d_in[7];
    float* out = (float*)d_out;

    const int g1_smem = G1_SMEM_FLOATS * 4;   // 197120 B
    const int g2_smem = G2_SMEM_FLOATS * 4;   // 131328 B
    cudaFuncSetAttribute(k_gemm1, cudaFuncAttributeMaxDynamicSharedMemorySize, g1_smem);
    cudaFuncSetAttribute(k_gemm2, cudaFuncAttributeMaxDynamicSharedMemorySize, g2_smem);

    k_init   <<<(NN + 255) / 256, 256>>>((const int*)ei);
    k_convert<<<(NE + 255) / 256, 256>>>(ei);
    k_scan_a <<<NB, SB>>>();
    k_scan_b <<<1, 128>>>();
    k_scan_c <<<NB, SB>>>();
    k_fill   <<<(NE + 255) / 256, 256>>>();
    k_agg1   <<<(NN * 8 + 255) / 256, 256>>>(x);
    k_gemm1  <<<148, 512, g1_smem>>>(x, W1_rel, b1, W1_root);
    k_gemm2  <<<148, 512, g2_smem>>>(W2_rel, b2, W2_root, out);
    k_agg2   <<<(NN * 16 + 255) / 256, 256>>>(out);
}

// round 10
// speedup vs baseline: 1.4769x; 1.1322x over previous
#include <cuda_runtime.h>

#define NN  50000
#define FI  96
#define HID 128
#define FO  64
#define NE  800000

typedef unsigned long long u64;

// ---------------- device scratch (no allocations allowed) ----------------
__device__ __align__(16) int   g_src[NE];
__device__ __align__(16) int   g_dst[NE];
__device__ __align__(16) int   g_deg[NN];        // zero-init; re-zeroed by k_agg1 each call
__device__ __align__(16) int   g_off[NN];
__device__ __align__(16) int   g_cur[NN];        // after k_fill: g_cur[n] == end of node n
__device__ __align__(16) int   g_csr_src[NE];
__device__ __align__(16) float g_agg1[(size_t)NN * FI];   // 19.2 MB
__device__ __align__(16) float g_h[(size_t)NN * HID];     // 25.6 MB
__device__ __align__(16) float g_p[(size_t)NN * FO];      // 12.8 MB
__device__ int g_total;                           // zero-init; re-zeroed by k_agg1

// ---------------- f32x2 helpers (sm_103a packed FP32) ----------------
__device__ __forceinline__ u64 fma2(u64 a, u64 b, u64 c) {
    u64 d;
    asm("fma.rn.f32x2 %0, %1, %2, %3;" : "=l"(d) : "l"(a), "l"(b), "l"(c));
    return d;
}
__device__ __forceinline__ u64 dup2(float f) {
    u64 v;
    asm("mov.b64 %0, {%1, %1};" : "=l"(v) : "f"(f));
    return v;
}
__device__ __forceinline__ u64 lds_u64(const float* p) {
    u64 v;
    unsigned a = (unsigned)__cvta_generic_to_shared(p);
    asm("ld.shared.b64 %0, [%1];" : "=l"(v) : "r"(a));
    return v;
}
__device__ __forceinline__ void lds_v2u64(const float* p, u64& x, u64& y) {
    unsigned a = (unsigned)__cvta_generic_to_shared(p);
    asm("ld.shared.v2.u64 {%0, %1}, [%2];" : "=l"(x), "=l"(y) : "r"(a));
}
__device__ __forceinline__ float2 u2f(u64 v) {
    float2 f;
    asm("mov.b64 {%0, %1}, %2;" : "=f"(f.x), "=f"(f.y) : "l"(v));
    return f;
}
__device__ __forceinline__ void f4add(float4& a, float4 b) {
    a.x += b.x; a.y += b.y; a.z += b.z; a.w += b.w;
}

// ---------------- convert + per-dst histogram (per-block dtype vote) ----------------
__global__ __launch_bounds__(256) void k_convert(const void* __restrict__ ei) {
    __shared__ int nz;
    int t = threadIdx.x;
    if (t == 0) nz = 0;
    __syncthreads();
    // int64 edge_index with values < 50000 has every odd int32 word == 0
    if (((const int*)ei)[2 * t + 1] != 0) atomicAdd(&nz, 1);
    __syncthreads();
    bool is64 = (nz == 0);

    int e = blockIdx.x * 256 + t;
    if (e >= NE) return;
    int s, d;
    if (is64) {
        const long long* p = (const long long*)ei;
        s = (int)p[e]; d = (int)p[NE + e];
    } else {
        const int* p = (const int*)ei;
        s = p[e]; d = p[NE + e];
    }
    if (s < 0 || s >= NN || d < 0 || d >= NN) { s = 0; d = 0; }  // treated as self-loop
    g_src[e] = s;
    g_dst[e] = d;
    if (s != d) atomicAdd(&g_deg[d], 1);
}

// ---------------- slot assignment: unordered CSR offsets (no scan needed) ----------------
__global__ void k_assign() {
    int i = blockIdx.x * blockDim.x + threadIdx.x;
    if (i >= NN) return;
    int d = g_deg[i];
    int off = atomicAdd(&g_total, d);   // uniform-addr -> warp-aggregated REDUX
    g_off[i] = off;
    g_cur[i] = off;
}

// ---------------- CSR fill: csr_src grouped by dst ----------------
__global__ void k_fill() {
    int e = blockIdx.x * blockDim.x + threadIdx.x;
    if (e >= NE) return;
    int s = g_src[e], d = g_dst[e];
    if (s == d) return;
    int pos = atomicAdd(&g_cur[d], 1);
    g_csr_src[pos] = s;
}

// ---------------- agg1 gather: agg1[n] = sum_{e: dst=n} x[src[e]], 8 thr/node ----------------
// also zeroes g_deg / g_total for the next replay (dead after k_fill)
__global__ void k_agg1(const float* __restrict__ x) {
    int gid = blockIdx.x * blockDim.x + threadIdx.x;
    if (gid < NN) g_deg[gid] = 0;
    if (gid == 0) g_total = 0;
    int node = gid >> 3;
    int c = gid & 7;
    if (node >= NN) return;
    int i = g_off[node], end = g_cur[node];
    float4 a0 = make_float4(0.f, 0.f, 0.f, 0.f), a1 = a0, a2 = a0;
    int s = (i < end) ? g_csr_src[i] : 0;
    while (i < end) {
        int snext = (i + 1 < end) ? g_csr_src[i + 1] : 0;
        const float4* xs = (const float4*)(x + (size_t)s * FI);
        f4add(a0, xs[c]);
        f4add(a1, xs[c + 8]);
        f4add(a2, xs[c + 16]);
        s = snext;
        i++;
    }
    float4* ad = (float4*)(g_agg1 + (size_t)node * FI);
    ad[c] = a0; ad[c + 8] = a1; ad[c + 16] = a2;
}

// ---------------- gemm1: h = relu(agg1@W1_rel^T + x@W1_root^T + b1) ----------------
// FFMA2; W in smem (transposed), activations via warp-uniform broadcast LDG.128.
// Each warp: 8 nodes, lane covers outputs [4*lane, 4*lane+4).
#define G1_SMEM_BYTES ((24576 + 128) * 4)    // 98816 B

__global__ __launch_bounds__(512, 1)
void k_gemm1(const float* __restrict__ x, const float* __restrict__ Wrel,
             const float* __restrict__ b, const float* __restrict__ Wroot) {
    extern __shared__ float sm[];
    float* sWrel  = sm;                 // [96][128] transposed
    float* sWroot = sm + 12288;
    float* sb     = sm + 24576;
    int tid  = threadIdx.x;
    int warp = tid >> 5, lane = tid & 31;

    for (int i = tid; i < 12288; i += 512) {
        int j = i / FI, k = i - j * FI;          // src = W[j][k]
        sWrel [k * HID + j] = Wrel [i];
        sWroot[k * HID + j] = Wroot[i];
    }
    if (tid < HID) sb[tid] = b[tid];
    __syncthreads();

    const float* wrB = sWrel  + lane * 4;
    const float* woB = sWroot + lane * 4;

    for (int g = blockIdx.x * 16 + warp; g < NN / 8; g += gridDim.x * 16) {
        int node0 = g * 8;
        u64 accA[8], accB[8];
#pragma unroll
        for (int n = 0; n < 8; n++) { accA[n] = 0ull; accB[n] = 0ull; }

#pragma unroll 1
        for (int kc = 0; kc < FI; kc += 4) {
            u64 wr[4][2], wo[4][2];
#pragma unroll
            for (int kk = 0; kk < 4; kk++) {
                lds_v2u64(wrB + (kc + kk) * HID, wr[kk][0], wr[kk][1]);
                lds_v2u64(woB + (kc + kk) * HID, wo[kk][0], wo[kk][1]);
            }
#pragma unroll
            for (int n = 0; n < 8; n++) {
                float4 a4 = *(const float4*)(g_agg1 + (size_t)(node0 + n) * FI + kc);
                float4 x4 = *(const float4*)(x      + (size_t)(node0 + n) * FI + kc);
#define STEP1(kk, av, xv)                                          \
                { u64 aa = dup2(av), xx = dup2(xv);                \
                  accA[n] = fma2(aa, wr[kk][0], accA[n]);          \
                  accB[n] = fma2(aa, wr[kk][1], accB[n]);          \
                  accA[n] = fma2(xx, wo[kk][0], accA[n]);          \
                  accB[n] = fma2(xx, wo[kk][1], accB[n]); }
                STEP1(0, a4.x, x4.x)
                STEP1(1, a4.y, x4.y)
                STEP1(2, a4.z, x4.z)
                STEP1(3, a4.w, x4.w)
#undef STEP1
            }
        }
        float4 bb = ((const float4*)sb)[lane];
#pragma unroll
        for (int n = 0; n < 8; n++) {
            float2 lo = u2f(accA[n]), hi = u2f(accB[n]);
            float4 r;
            r.x = fmaxf(lo.x + bb.x, 0.f);
            r.y = fmaxf(lo.y + bb.y, 0.f);
            r.z = fmaxf(hi.x + bb.z, 0.f);
            r.w = fmaxf(hi.y + bb.w, 0.f);
            ((float4*)(g_h + (size_t)(node0 + n) * HID))[lane] = r;
        }
    }
}

// ---------------- gemm2: p = h@W2_rel^T ; out = h@W2_root^T + b2 ----------------
// Each warp: 8 nodes, lane covers outputs [2*lane, 2*lane+2).
#define G2_SMEM_BYTES ((16384 + 64) * 4)     // 65792 B

__global__ __launch_bounds__(512, 1)
void k_gemm2(const float* __restrict__ Wrel, const float* __restrict__ b,
             const float* __restrict__ Wroot, float* __restrict__ out) {
    extern __shared__ float sm[];
    float* sWrel  = sm;                 // [128][64] transposed
    float* sWroot = sm + 8192;
    float* sb     = sm + 16384;
    int tid  = threadIdx.x;
    int warp = tid >> 5, lane = tid & 31;

    for (int i = tid; i < 8192; i += 512) {
        int j = i >> 7, k = i & 127;     // src = W[j][k]
        sWrel [k * FO + j] = Wrel [i];
        sWroot[k * FO + j] = Wroot[i];
    }
    if (tid < FO) sb[tid] = b[tid];
    __syncthreads();

    const float* wrB = sWrel  + lane * 2;
    const float* woB = sWroot + lane * 2;

    for (int g = blockIdx.x * 16 + warp; g < NN / 8; g += gridDim.x * 16) {
        int node0 = g * 8;
        u64 accP[8], accO[8];
#pragma unroll
        for (int n = 0; n < 8; n++) { accP[n] = 0ull; accO[n] = 0ull; }

#pragma unroll 1
        for (int kc = 0; kc < HID; kc += 4) {
            u64 wr[4], wo[4];
#pragma unroll
            for (int kk = 0; kk < 4; kk++) {
                wr[kk] = lds_u64(wrB + (kc + kk) * FO);
                wo[kk] = lds_u64(woB + (kc + kk) * FO);
            }
#pragma unroll
            for (int n = 0; n < 8; n++) {
                float4 h4 = *(const float4*)(g_h + (size_t)(node0 + n) * HID + kc);
#define STEP2(kk, hv)                                              \
                { u64 hh = dup2(hv);                               \
                  accP[n] = fma2(hh, wr[kk], accP[n]);             \
                  accO[n] = fma2(hh, wo[kk], accO[n]); }
                STEP2(0, h4.x)
                STEP2(1, h4.y)
                STEP2(2, h4.z)
                STEP2(3, h4.w)
#undef STEP2
            }
        }
        float2 bb = ((const float2*)sb)[lane];
#pragma unroll
        for (int n = 0; n < 8; n++) {
            float2 pv = u2f(accP[n]);
            ((float2*)(g_p + (size_t)(node0 + n) * FO))[lane] = pv;
            float2 ov = u2f(accO[n]);
            ov.x += bb.x; ov.y += bb.y;
            ((float2*)(out + (size_t)(node0 + n) * FO))[lane] = ov;
        }
    }
}

// ---------------- agg2 gather: out[n] += sum_{e: dst=n} p[src[e]], 16 thr/node ----------------
__global__ void k_agg2(float* __restrict__ out) {
    int gid = blockIdx.x * blockDim.x + threadIdx.x;
    int node = gid >> 4;
    int c = gid & 15;
    if (node >= NN) return;
    int i = g_off[node], end = g_cur[node];
    float4 acc = make_float4(0.f, 0.f, 0.f, 0.f);
    int s = (i < end) ? g_csr_src[i] : 0;
    while (i < end) {
        int snext = (i + 1 < end) ? g_csr_src[i + 1] : 0;
        f4add(acc, ((const float4*)(g_p + (size_t)s * FO))[c]);
        s = snext;
        i++;
    }
    float4* od = (float4*)(out + (size_t)node * FO);
    float4 cur = od[c];
    f4add(cur, acc);
    od[c] = cur;
}

// ---------------- launch ----------------
extern "C" void kernel_launch(void* const* d_in, const int* in_sizes, int n_in,
                              void* d_out, int out_size) {
    const float* x       = (const float*)d_in[0];
    const void*  ei      = d_in[1];
    const float* W1_rel  = (const float*)d_in[2];
    const float* b1      = (const float*)d_in[3];
    const float* W1_root = (const float*)d_in[4];
    const float* W2_rel  = (const float*)d_in[5];
    const float* b2      = (const float*)d_in[6];
    const float* W2_root = (const float*)d_in[7];
    float* out = (float*)d_out;

    cudaFuncSetAttribute(k_gemm1, cudaFuncAttributeMaxDynamicSharedMemorySize, G1_SMEM_BYTES);
    cudaFuncSetAttribute(k_gemm2, cudaFuncAttributeMaxDynamicSharedMemorySize, G2_SMEM_BYTES);

    k_convert<<<(NE + 255) / 256, 256>>>(ei);          // 1
    k_assign <<<(NN + 255) / 256, 256>>>();            // 2
    k_fill   <<<(NE + 255) / 256, 256>>>();            // 3
    k_agg1   <<<(NN * 8 + 255) / 256, 256>>>(x);       // 4  <- profiled slot
    k_gemm1  <<<148, 512, G1_SMEM_BYTES>>>(x, W1_rel, b1, W1_root);   // 5
    k_gemm2  <<<148, 512, G2_SMEM_BYTES>>>(W2_rel, b2, W2_root, out); // 6
    k_agg2   <<<(NN * 16 + 255) / 256, 256>>>(out);    // 7
}